// round 17
// baseline (speedup 1.0000x reference)
#include <cuda_runtime.h>
#include <cstdint>

// ---------------- scratch (device globals; zero-initialized, no alloc) -------
__device__ float g_kv  [16LL * 1024 * 1024];   // cols 0..511 = k, 512..1023 = v
__device__ float g_q   [16LL * 2048 * 512];
__device__ float g_att [16LL * 2048 * 1024];
__device__ float g_vmel[16LL * 1024 * 1280];
__device__ float g_phc [16LL * 1024 * 512];
__device__ float g_wqc [2560LL * 512];
__device__ float g_wmc [512LL * 1280];
__device__ float g_wkv [512LL * 1024];
__device__ float g_bkv [1024];
__device__ int   g_len[16];

// -------- lengths dtype sniffing (reference says int64; JAX x64-off -> int32)
__global__ void normalize_lengths(const void* __restrict__ lp)
{
    const long long* l8 = (const long long*)lp;
    const int*       l4 = (const int*)lp;
    bool ok64 = true;
    for (int i = 0; i < 8; ++i) {
        long long v = l8[i];
        if (v < 1 || v > 1024) ok64 = false;
    }
    if (ok64) { for (int i = 0; i < 16; ++i) g_len[i] = (int)l8[i]; }
    else      { for (int i = 0; i < 16; ++i) g_len[i] = l4[i]; }
}

// ---------------------------------------------------------------------------
__device__ __forceinline__ unsigned f2tf(float x) {
    unsigned u; asm("cvt.rna.tf32.f32 %0, %1;" : "=r"(u) : "f"(x)); return u;
}
__device__ __forceinline__ void mma8(float* c, const unsigned* a,
                                     unsigned b0, unsigned b1) {
    asm volatile(
        "mma.sync.aligned.m16n8k8.row.col.f32.tf32.tf32.f32 "
        "{%0,%1,%2,%3},{%4,%5,%6,%7},{%8,%9},{%0,%1,%2,%3};"
        : "+f"(c[0]), "+f"(c[1]), "+f"(c[2]), "+f"(c[3])
        : "r"(a[0]), "r"(a[1]), "r"(a[2]), "r"(a[3]), "r"(b0), "r"(b1));
}
__device__ __forceinline__ void cp16(unsigned dst, const void* src) {
    asm volatile("cp.async.cg.shared.global [%0], [%1], 16;"
                 :: "r"(dst), "l"(src) : "memory");
}
#define CP_COMMIT() asm volatile("cp.async.commit_group;" ::: "memory")
#define CP_WAIT0()  asm volatile("cp.async.wait_group 0;" ::: "memory")

// -------- one-time tf32 pre-round of raw inputs ------------------------------
__global__ __launch_bounds__(256) void cvt_copy(
    const float4* __restrict__ src, float4* __restrict__ dst, int n4)
{
    int i = blockIdx.x * 256 + threadIdx.x;
    if (i >= n4) return;
    float4 v = src[i];
    uint4 u; u.x = f2tf(v.x); u.y = f2tf(v.y); u.z = f2tf(v.z); u.w = f2tf(v.w);
    dst[i] = *(float4*)&u;
}
// wkv[k][0..511]=Wk[k][:], wkv[k][512..1023]=Wv[k][:]  (tf32-rounded)
__global__ __launch_bounds__(256) void cvt_concat(
    const float* __restrict__ Wk, const float* __restrict__ Wv,
    float4* __restrict__ dst)
{
    int i = blockIdx.x * 256 + threadIdx.x;      // 512*256 float4s
    int row = i >> 8, c4 = i & 255;
    const float4* src = (c4 < 128)
        ? (const float4*)(Wk + (long long)row * 512) + c4
        : (const float4*)(Wv + (long long)row * 512) + (c4 - 128);
    float4 v = *src;
    uint4 u; u.x = f2tf(v.x); u.y = f2tf(v.y); u.z = f2tf(v.z); u.w = f2tf(v.w);
    dst[i] = *(float4*)&u;
}
__global__ void concat_bias(const float* __restrict__ bk,
                            const float* __restrict__ bv)
{
    int i = blockIdx.x * 256 + threadIdx.x;
    if (i < 512) g_bkv[i] = bk[i];
    else if (i < 1024) g_bkv[i] = bv[i - 512];
}

// ---------------------------------------------------------------------------
// tf32 tensor-core GEMM, 128x128x32 CTA tiles, 128 threads (4 warps 2m x 2n),
// warp tile 64x64, m16n8k8. 2-stage cp.async pipeline, one barrier per K=32
// (fills for stage it+1 issued AFTER barrier it: buffer buf^1's last readers
// were compute it-1, ordered by that barrier). 2 CTAs/SM.
// AT=0: A row-major [M,K] -> smem As[m][36]; AT=1: A k-major [K,M] -> As[k][136].
// BT=0: B [K,N] -> Bs[k][136]; BT=1: B^T [N,K] -> Bs[n][36].
// All operands are tf32 bits in gmem (pre-rounded), except g (MMA truncates).
// EPI=0: C = alpha*acc + bias[col] (opt); EPI=2: mel permute (rows=mel, cols=t).
// OT=1: epilogue stores tf32-rounded bits (output consumed only by GEMMs).
// LM: 0=none; 1=skip M-block when (r0&1023)>=len[r0>>10]; 2=skip CTA when
// c0>=len[z]; 3=clamp K iters to ceil(len[z]/32); 4=skip CTA when r0>=len[z].
template<int AT, int BT, int EPI, int LM, int OT>
__global__ __launch_bounds__(128, 2) void tc_gemm(
    const float* __restrict__ A, const float* __restrict__ Bm,
    const float* __restrict__ bias, float* __restrict__ C,
    int K, int lda, int ldb, int ldc,
    long long sA, long long sB, long long sC, float alpha)
{
    constexpr int ASZ = AT ? 32 * 136 : 128 * 36;
    constexpr int BSZ = BT ? 128 * 36 : 32 * 136;
    __shared__ __align__(16) unsigned smA[2][ASZ];
    __shared__ __align__(16) unsigned smB[2][BSZ];

    const int r0 = blockIdx.y * 128, c0 = blockIdx.x * 128;
    if (LM == 1) { if ((r0 & 1023) >= g_len[r0 >> 10]) return; }
    if (LM == 2) { if (c0 >= g_len[blockIdx.z]) return; }
    if (LM == 4) { if (r0 >= g_len[blockIdx.z]) return; }

    A  += blockIdx.z * sA;
    Bm += blockIdx.z * sB;
    const int tid  = threadIdx.x;
    const int lane = tid & 31, warp = tid >> 5;
    const int g  = lane >> 2, tg = lane & 3;
    const int wm = warp & 1,  wn = warp >> 1;

    const unsigned smA_u = (unsigned)__cvta_generic_to_shared(&smA[0][0]);
    const unsigned smB_u = (unsigned)__cvta_generic_to_shared(&smB[0][0]);

    // single-base fill addressing: 8 chunks of 16B per operand per thread
    long long aoff, astp; unsigned adst, adstp;
    if (!AT) { int m = tid >> 3, kq = (tid & 7) * 4;
               aoff = (long long)(r0 + m) * lda + kq; astp = 16LL * lda;
               adst = m * 36 + kq;  adstp = 16 * 36; }
    else     { int k = tid >> 5, m4 = (tid & 31) * 4;
               aoff = (long long)k * lda + r0 + m4;   astp = 4LL * lda;
               adst = k * 136 + m4; adstp = 4 * 136; }
    long long boff, bstp; unsigned bdst, bdstp;
    if (!BT) { int k = tid >> 5, n4 = (tid & 31) * 4;
               boff = (long long)k * ldb + c0 + n4;   bstp = 4LL * ldb;
               bdst = k * 136 + n4; bdstp = 4 * 136; }
    else     { int n = tid >> 3, kq = (tid & 7) * 4;
               boff = (long long)(c0 + n) * ldb + kq; bstp = 16LL * ldb;
               bdst = n * 36 + kq;  bdstp = 16 * 36; }
    const long long adv_a = AT ? 32LL : 32;    // element advance along K
    const long long aadv  = AT ? 32LL * lda : 32LL;
    const long long badv  = BT ? 32LL : 32LL * ldb;
    (void)adv_a;

    float acc[4][8][4] = {};
    int nIter = K >> 5;
    if (LM == 3) {
        int nl = (g_len[blockIdx.z] + 31) >> 5;
        if (nl < nIter) nIter = nl;
    }

    // prologue: stage 0 into buffer 0
    #pragma unroll
    for (int r = 0; r < 8; ++r) {
        cp16(smA_u + (adst + (unsigned)r * adstp) * 4u, A + aoff + r * astp);
        cp16(smB_u + (bdst + (unsigned)r * bdstp) * 4u, Bm + boff + r * bstp);
    }
    CP_COMMIT();
    aoff += aadv; boff += badv;

    int buf = 0;
    for (int it = 0; it < nIter; ++it) {
        CP_WAIT0();          // stage it landed
        __syncthreads();     // visible; buffer buf^1 drained (read at it-1)
        if (it + 1 < nIter) {
            const unsigned nb = (unsigned)(buf ^ 1);
            #pragma unroll
            for (int r = 0; r < 8; ++r) {
                cp16(smA_u + nb * (ASZ * 4u) + (adst + (unsigned)r * adstp) * 4u,
                     A + aoff + r * astp);
                cp16(smB_u + nb * (BSZ * 4u) + (bdst + (unsigned)r * bdstp) * 4u,
                     Bm + boff + r * bstp);
            }
            aoff += aadv; boff += badv;
        }
        CP_COMMIT();
        const unsigned* As = smA[buf];
        const unsigned* Bs = smB[buf];
        #pragma unroll
        for (int kk = 0; kk < 32; kk += 8) {
            unsigned af[4][4];
            const int k = kk + tg;
            #pragma unroll
            for (int mi = 0; mi < 4; ++mi) {
                int m = wm * 64 + mi * 16 + g;
                if (!AT) {
                    af[mi][0] = As[m * 36 + k];
                    af[mi][1] = As[(m + 8) * 36 + k];
                    af[mi][2] = As[m * 36 + k + 4];
                    af[mi][3] = As[(m + 8) * 36 + k + 4];
                } else {
                    af[mi][0] = As[k * 136 + m];
                    af[mi][1] = As[k * 136 + m + 8];
                    af[mi][2] = As[(k + 4) * 136 + m];
                    af[mi][3] = As[(k + 4) * 136 + m + 8];
                }
            }
            #pragma unroll
            for (int ni = 0; ni < 8; ++ni) {
                int n = wn * 64 + ni * 8 + g;
                unsigned b0, b1;
                if (!BT) { b0 = Bs[k * 136 + n]; b1 = Bs[(k + 4) * 136 + n]; }
                else     { b0 = Bs[n * 36 + k];  b1 = Bs[n * 36 + k + 4]; }
                #pragma unroll
                for (int mi = 0; mi < 4; ++mi)
                    mma8(acc[mi][ni], af[mi], b0, b1);
            }
        }
        buf ^= 1;
    }

    if (EPI == 2) {
        const int b = blockIdx.z;
        #pragma unroll
        for (int mi = 0; mi < 4; ++mi) {
            int row = r0 + wm * 64 + mi * 16 + g;
            #pragma unroll
            for (int rr = 0; rr < 2; ++rr) {
                int mel = row + rr * 8;
                float bb = bias[mel];
                float* op = C + ((long long)(b * 64 + (mel & 63)) * 20 + (mel >> 6)) * 2048;
                #pragma unroll
                for (int ni = 0; ni < 8; ++ni) {
                    int t = c0 + wn * 64 + ni * 8 + 2 * tg;
                    float2 v;
                    v.x = acc[mi][ni][rr * 2 + 0] + bb;
                    v.y = acc[mi][ni][rr * 2 + 1] + bb;
                    *(float2*)(op + t) = v;
                }
            }
        }
    } else {
        C += blockIdx.z * sC;
        #pragma unroll
        for (int mi = 0; mi < 4; ++mi) {
            int row = r0 + wm * 64 + mi * 16 + g;
            #pragma unroll
            for (int ni = 0; ni < 8; ++ni) {
                int col = c0 + wn * 64 + ni * 8 + 2 * tg;
                float b0v = bias ? bias[col] : 0.f;
                float b1v = bias ? bias[col + 1] : 0.f;
                float o0 = alpha * acc[mi][ni][0] + b0v;
                float o1 = alpha * acc[mi][ni][1] + b1v;
                float o2 = alpha * acc[mi][ni][2] + b0v;
                float o3 = alpha * acc[mi][ni][3] + b1v;
                float2 v0, v1;
                if (OT) {
                    v0.x = __uint_as_float(f2tf(o0));
                    v0.y = __uint_as_float(f2tf(o1));
                    v1.x = __uint_as_float(f2tf(o2));
                    v1.y = __uint_as_float(f2tf(o3));
                } else { v0.x = o0; v0.y = o1; v1.x = o2; v1.y = o3; }
                *(float2*)(C + (long long)row * ldc + col)       = v0;
                *(float2*)(C + (long long)(row + 8) * ldc + col) = v1;
            }
        }
    }
}

// -------- masked softmax, zero-fill to roundup32(len); tf32-rounded output ---
__global__ __launch_bounds__(256) void softmax_rows(float* __restrict__ att)
{
    const int row = blockIdx.x;
    const int b = row >> 11;
    float* p = att + (long long)row * 1024;
    const int len = g_len[b];
    const int lim = (len + 31) & ~31;       // final GEMM clamps K at 32-granularity
    const int tid = threadIdx.x;
    const int s0 = tid * 4;
    const bool act = s0 < lim;
    float4 v = make_float4(0.f, 0.f, 0.f, 0.f);
    if (act) v = ((const float4*)p)[tid];
    float vals[4] = {v.x, v.y, v.z, v.w};
    float mx = -1e30f;
    #pragma unroll
    for (int u = 0; u < 4; ++u)
        if (s0 + u < len && vals[u] > mx) mx = vals[u];
    __shared__ float red[8];
    #pragma unroll
    for (int off = 16; off > 0; off >>= 1)
        mx = fmaxf(mx, __shfl_xor_sync(0xffffffffu, mx, off));
    if ((tid & 31) == 0) red[tid >> 5] = mx;
    __syncthreads();
    mx = red[0];
    #pragma unroll
    for (int i = 1; i < 8; ++i) mx = fmaxf(mx, red[i]);
    __syncthreads();
    float sum = 0.f;
    #pragma unroll
    for (int u = 0; u < 4; ++u) {
        float e = (s0 + u < len) ? __expf(vals[u] - mx) : 0.f;
        vals[u] = e; sum += e;
    }
    #pragma unroll
    for (int off = 16; off > 0; off >>= 1)
        sum += __shfl_xor_sync(0xffffffffu, sum, off);
    if ((tid & 31) == 0) red[tid >> 5] = sum;
    __syncthreads();
    sum = 0.f;
    #pragma unroll
    for (int i = 0; i < 8; ++i) sum += red[i];
    const float inv = 1.f / sum;
    if (act) {
        v.x = __uint_as_float(f2tf(vals[0] * inv));
        v.y = __uint_as_float(f2tf(vals[1] * inv));
        v.z = __uint_as_float(f2tf(vals[2] * inv));
        v.w = __uint_as_float(f2tf(vals[3] * inv));
        ((float4*)p)[tid] = v;
    }
}

// ---------------------------------------------------------------------------
extern "C" void kernel_launch(void* const* d_in, const int* in_sizes, int n_in,
                              void* d_out, int out_size)
{
    const float* ph      = (const float*)d_in[0];
    const float* g       = (const float*)d_in[1];
    const void*  lengths = d_in[2];
    const float* Wk      = (const float*)d_in[3];
    const float* bk      = (const float*)d_in[4];
    const float* Wv      = (const float*)d_in[5];
    const float* bv      = (const float*)d_in[6];
    const float* Wq      = (const float*)d_in[7];
    const float* bq      = (const float*)d_in[8];
    const float* Wmel    = (const float*)d_in[9];
    const float* bmel    = (const float*)d_in[10];
    float* out = (float*)d_out;

    float *kv_, *q_, *att_, *vmel_, *phc_, *wqc_, *wmc_, *wkv_, *bkv_;
    cudaGetSymbolAddress((void**)&kv_,   g_kv);
    cudaGetSymbolAddress((void**)&q_,    g_q);
    cudaGetSymbolAddress((void**)&att_,  g_att);
    cudaGetSymbolAddress((void**)&vmel_, g_vmel);
    cudaGetSymbolAddress((void**)&phc_,  g_phc);
    cudaGetSymbolAddress((void**)&wqc_,  g_wqc);
    cudaGetSymbolAddress((void**)&wmc_,  g_wmc);
    cudaGetSymbolAddress((void**)&wkv_,  g_wkv);
    cudaGetSymbolAddress((void**)&bkv_,  g_bkv);

    const dim3 th(128);

    normalize_lengths<<<1, 1>>>(lengths);

    // pre-round raw inputs (except g) to tf32 bits; build concat kv weights
    cvt_copy<<<8192, 256>>>((const float4*)ph,   (float4*)phc_, 2097152);
    cvt_copy<<<1280, 256>>>((const float4*)Wq,   (float4*)wqc_, 327680);
    cvt_copy<<<640,  256>>>((const float4*)Wmel, (float4*)wmc_, 163840);
    cvt_concat<<<512, 256>>>(Wk, Wv, (float4*)wkv_);
    concat_bias<<<4, 256>>>(bk, bv);

    // kv = ph@[Wk|Wv] + [bk|bv]   (skip s-blocks >= len[b])
    tc_gemm<0,0,0,1,1><<<dim3(8, 128, 1), th>>>(phc_, wkv_, bkv_, kv_,
        512, 512, 1024, 1024, 0, 0, 0, 1.f);

    // q = g^T@Wq + bq  (A = g raw k-major — MMA truncates; B pre-rounded)
    tc_gemm<1,0,0,0,1><<<dim3(4, 16, 16), th>>>(g, wqc_, bq, q_,
        2560, 2048, 512, 512, 2560LL * 2048, 0, 2048LL * 512, 1.f);

    // att = scale * q@k^T  (B^T = kv rows, k half; skip CTAs with c0 >= len)
    tc_gemm<0,1,0,2,0><<<dim3(8, 16, 16), th>>>(q_, kv_, nullptr, att_,
        512, 512, 1024, 1024, 2048LL * 512, 1024LL * 1024, 2048LL * 1024,
        0.04419417382415922f);

    softmax_rows<<<32768, 256>>>(att_);

    // vmel = v@Wmel  (A = kv v-half; skip s-blocks >= len[b])
    tc_gemm<0,0,0,4,1><<<dim3(10, 8, 16), th>>>(kv_ + 512, wmc_, nullptr, vmel_,
        512, 1024, 1280, 1280, 1024LL * 1024, 0, 1024LL * 1280, 1.f);

    // out = permute(att@vmel + bmel): rows=mel (A=vmel k-major), cols=t,
    // K=S clamped to ceil(len/32)*32
    tc_gemm<1,1,2,3,0><<<dim3(16, 10, 16), th>>>(vmel_, att_, bmel, out,
        1024, 1280, 1024, 2048, 1024LL * 1280, 2048LL * 1024, 0, 1.f);
}